// round 14
// baseline (speedup 1.0000x reference)
#include <cuda_runtime.h>
#include <cuda_fp16.h>

#define NN      50000
#define NE      1600000
#define IN_DIM  128
#define HID     64
#define NG      256
#define CAP     192          // max bucket capacity per node (true max deg ~70)

// ---------------- device scratch (no allocations allowed) ----------------
__device__ __align__(16) __half g_bufAh[NN * HID]; // h' = dinv*(X@W), fp16
__device__ __align__(16) float  g_bufB[NN * HID];  // aggregation output, fp32
__device__ int   g_cursor[NN];                     // bucket fill cursors (= in-degree)
__device__ int   g_src[(size_t)NN * CAP];          // bucketed source ids
__device__ float g_psum[NG * HID];
__device__ float g_pcnt[NG];
__device__ int   g_ei64;               // edge_index is int64?
__device__ int   g_b64;                // batch is int64?

__device__ __forceinline__ int eidx(const void* p, long long i) {
    return g_ei64 ? (int)((const long long*)p)[i] : ((const int*)p)[i];
}

// ---------------- kernels ----------------
// detect index dtypes: one warp, ballot
__global__ void k_detect(const void* __restrict__ ei, const void* __restrict__ batch) {
    int lane = threadIdx.x;
    const long long* e64 = (const long long*)ei;
    long long v = e64[lane];
    unsigned ok = __ballot_sync(0xffffffffu, v >= 0 && v < NN);
    if (lane == 0) g_ei64 = (ok == 0xffffffffu);
    if (lane == 0) {
        long long bv = ((const long long*)batch)[NN / 2 - 1];
        g_b64 = (bv >= 0 && bv < NG) ? 1 : 0;
    }
}

// single pass: bucket every edge by target
__global__ void k_fill(const void* __restrict__ ei) {
    int e = blockIdx.x * blockDim.x + threadIdx.x;
    if (e >= NE) return;
    int r = eidx(ei, e);
    int c = eidx(ei, (long long)NE + e);
    int slot = atomicAdd(&g_cursor[c], 1);
    if (slot < CAP) g_src[(size_t)c * CAP + slot] = r;
}

// g_bufAh[n,:] = half( dinv[n] * (X[n,:K] @ W[K,64]) )
// 128 threads: 32 nodes x 64 cols per block; thread = 4 nodes (stride 8) x 4 cols
template<int K, bool FROM_EXT>
__global__ void __launch_bounds__(128) k_gemm(const float* __restrict__ Xext,
                                              const float* __restrict__ W) {
    constexpr int KC = 64;                    // k-chunk
    __shared__ float4 sW[KC * 16];            // [k][colquad]
    __shared__ float  sX[32 * KC];            // [node][k]
    const float* X = FROM_EXT ? Xext : (const float*)g_bufB;
    const int tid = threadIdx.x;
    const int node0 = blockIdx.x * 32;
    const int nn = min(32, NN - node0);
    const int tn = tid >> 4;                  // 0..7
    const int tc = tid & 15;                  // 0..15
    float4 acc[4];
    #pragma unroll
    for (int j = 0; j < 4; j++) acc[j] = make_float4(0.f, 0.f, 0.f, 0.f);

    for (int kc = 0; kc < K; kc += KC) {
        for (int i = tid; i < KC * 16; i += 128)
            sW[i] = ((const float4*)W)[(kc + (i >> 4)) * 16 + (i & 15)];
        for (int i = tid; i < 32 * (KC / 4); i += 128) {
            int nl = i / (KC / 4), kq = i % (KC / 4);
            float4 xv = (nl < nn)
                ? ((const float4*)X)[(size_t)(node0 + nl) * (K / 4) + (kc >> 2) + kq]
                : make_float4(0.f, 0.f, 0.f, 0.f);
            ((float4*)sX)[nl * (KC / 4) + kq] = xv;
        }
        __syncthreads();
        #pragma unroll 8
        for (int k = 0; k < KC; k++) {
            float4 w4 = sW[k * 16 + tc];
            #pragma unroll
            for (int j = 0; j < 4; j++) {
                float xv = sX[(tn + j * 8) * KC + k];
                acc[j].x = fmaf(xv, w4.x, acc[j].x);
                acc[j].y = fmaf(xv, w4.y, acc[j].y);
                acc[j].z = fmaf(xv, w4.z, acc[j].z);
                acc[j].w = fmaf(xv, w4.w, acc[j].w);
            }
        }
        __syncthreads();
    }
    #pragma unroll
    for (int j = 0; j < 4; j++) {
        int nl = tn + j * 8;
        if (nl < nn) {
            int node = node0 + nl;
            float s = rsqrtf((float)g_cursor[node] + 1.0f);
            float4 v = acc[j];
            __half2 lo = __floats2half2_rn(v.x * s, v.y * s);
            __half2 hi = __floats2half2_rn(v.z * s, v.w * s);
            uint2 pk = make_uint2(*(unsigned*)&lo, *(unsigned*)&hi);
            ((uint2*)g_bufAh)[node * 16 + tc] = pk;
        }
    }
}

// full warp per node: out = relu( dinv[c]*(h'[c] + sum h'[src]) + b )
// lane holds half2 (2 dims); edge ids broadcast-read by all lanes; x4 unroll
__global__ void k_aggr(const float* __restrict__ b, int fuse_pool,
                       const void* __restrict__ batch) {
    const int lane = threadIdx.x & 31;
    const int node = blockIdx.x * (blockDim.x >> 5) + (threadIdx.x >> 5);
    if (node >= NN) return;
    const __half2* __restrict__ h2 = (const __half2*)g_bufAh;  // row = 32 half2
    float2 acc = __half22float2(h2[node * 32 + lane]);          // self-loop h'
    const int cnt = g_cursor[node];
    const int deg = min(cnt, CAP);
    const int* __restrict__ bucket = &g_src[(size_t)node * CAP];
    int k = 0;
    for (; k + 4 <= deg; k += 4) {
        int r0 = __ldg(bucket + k);
        int r1 = __ldg(bucket + k + 1);
        int r2 = __ldg(bucket + k + 2);
        int r3 = __ldg(bucket + k + 3);
        __half2 v0 = h2[r0 * 32 + lane];
        __half2 v1 = h2[r1 * 32 + lane];
        __half2 v2 = h2[r2 * 32 + lane];
        __half2 v3 = h2[r3 * 32 + lane];
        float2 f0 = __half22float2(v0);
        float2 f1 = __half22float2(v1);
        float2 f2 = __half22float2(v2);
        float2 f3 = __half22float2(v3);
        acc.x += (f0.x + f1.x) + (f2.x + f3.x);
        acc.y += (f0.y + f1.y) + (f2.y + f3.y);
    }
    for (; k < deg; k++) {
        int r = __ldg(bucket + k);
        float2 f = __half22float2(h2[r * 32 + lane]);
        acc.x += f.x;
        acc.y += f.y;
    }
    const float d = rsqrtf((float)cnt + 1.0f);
    const float2 bb = ((const float2*)b)[lane];
    float2 v;
    v.x = fmaxf(fmaf(d, acc.x, bb.x), 0.f);
    v.y = fmaxf(fmaf(d, acc.y, bb.y), 0.f);
    if (!fuse_pool) {
        ((float2*)g_bufB)[node * 32 + lane] = v;
    } else {
        int g = g_b64 ? (int)((const long long*)batch)[node]
                      : ((const int*)batch)[node];
        float* ps = &g_psum[g * HID + lane * 2];
        atomicAdd(ps + 0, v.x);
        atomicAdd(ps + 1, v.y);
        if (lane == 0) atomicAdd(&g_pcnt[g], 1.0f);
    }
}

__global__ void k_mlp(const float* __restrict__ Wl1, const float* __restrict__ bl1,
                      const float* __restrict__ Wl2, const float* __restrict__ bl2,
                      float* __restrict__ out) {
    int g = threadIdx.x;
    if (g >= NG) return;
    float inv = 1.0f / fmaxf(g_pcnt[g], 1.0f);
    float mean[HID];
    #pragma unroll
    for (int k = 0; k < HID; k++) mean[k] = g_psum[g * HID + k] * inv;
    float o = bl2[0];
    #pragma unroll
    for (int j = 0; j < 16; j++) {
        float hj = bl1[j];
        #pragma unroll
        for (int k = 0; k < HID; k++) hj = fmaf(mean[k], Wl1[k * 16 + j], hj);
        o = fmaf(hj, Wl2[j], o);
    }
    out[g] = o;
}

// ---------------- launch ----------------
extern "C" void kernel_launch(void* const* d_in, const int* in_sizes, int n_in,
                              void* d_out, int out_size) {
    const float* x     = (const float*)d_in[0];
    const void*  ei    = d_in[1];
    const void*  batch = d_in[2];
    const float* W1 = (const float*)d_in[3];
    const float* b1 = (const float*)d_in[4];
    const float* W2 = (const float*)d_in[5];
    const float* b2 = (const float*)d_in[6];
    const float* W3 = (const float*)d_in[7];
    const float* b3 = (const float*)d_in[8];
    const float* Wl1 = (const float*)d_in[9];
    const float* bl1 = (const float*)d_in[10];
    const float* Wl2 = (const float*)d_in[11];
    const float* bl2 = (const float*)d_in[12];
    float* out = (float*)d_out;

    // zero the small scratch via memset (graph-capturable)
    void* curPtr;  cudaGetSymbolAddress(&curPtr,  g_cursor);
    void* psumPtr; cudaGetSymbolAddress(&psumPtr, g_psum);
    void* pcntPtr; cudaGetSymbolAddress(&pcntPtr, g_pcnt);
    cudaMemsetAsync(curPtr,  0, NN * sizeof(int));
    cudaMemsetAsync(psumPtr, 0, NG * HID * sizeof(float));
    cudaMemsetAsync(pcntPtr, 0, NG * sizeof(float));

    const int T = 512;
    k_detect<<<1, 32>>>(ei, batch);
    k_fill<<<(NE + T - 1) / T, T>>>(ei);

    const int gemmBlocks = (NN + 31) / 32;
    const int aggrBlocks = (NN + 7) / 8;    // 8 warps/block

    k_gemm<128, true ><<<gemmBlocks, 128>>>(x, W1);
    k_aggr<<<aggrBlocks, 256>>>(b1, 0, batch);
    k_gemm<64,  false><<<gemmBlocks, 128>>>(nullptr, W2);
    k_aggr<<<aggrBlocks, 256>>>(b2, 0, batch);
    k_gemm<64,  false><<<gemmBlocks, 128>>>(nullptr, W3);
    k_aggr<<<aggrBlocks, 256>>>(b3, 1, batch);   // fused mean-pool

    k_mlp<<<1, NG>>>(Wl1, bl1, Wl2, bl2, out);
}

// round 15
// speedup vs baseline: 1.0371x; 1.0371x over previous
#include <cuda_runtime.h>
#include <cuda_fp16.h>

#define NN      50000
#define NE      1600000
#define IN_DIM  128
#define HID     64
#define NG      256
#define CAP     192          // max bucket capacity per node (true max deg ~70)

// ---------------- device scratch (no allocations allowed) ----------------
__device__ __align__(16) __half g_bufAh[NN * HID]; // h' = dinv*(X@W), fp16
__device__ __align__(16) float  g_bufB[NN * HID];  // aggregation output, fp32
__device__ int   g_cursor[NN];                     // bucket fill cursors (= in-degree)
__device__ int   g_src[(size_t)NN * CAP];          // bucketed source ids
__device__ float g_psum[NG * HID];
__device__ float g_pcnt[NG];
__device__ int   g_ei64;               // edge_index is int64?
__device__ int   g_b64;                // batch is int64?

__device__ __forceinline__ int eidx(const void* p, long long i) {
    return g_ei64 ? (int)((const long long*)p)[i] : ((const int*)p)[i];
}

// ---------------- kernels ----------------
// detect index dtypes: one warp, ballot
__global__ void k_detect(const void* __restrict__ ei, const void* __restrict__ batch) {
    int lane = threadIdx.x;
    const long long* e64 = (const long long*)ei;
    long long v = e64[lane];
    unsigned ok = __ballot_sync(0xffffffffu, v >= 0 && v < NN);
    if (lane == 0) g_ei64 = (ok == 0xffffffffu);
    if (lane == 0) {
        long long bv = ((const long long*)batch)[NN / 2 - 1];
        g_b64 = (bv >= 0 && bv < NG) ? 1 : 0;
    }
}

// single pass: bucket every edge by target
__global__ void k_fill(const void* __restrict__ ei) {
    int e = blockIdx.x * blockDim.x + threadIdx.x;
    if (e >= NE) return;
    int r = eidx(ei, e);
    int c = eidx(ei, (long long)NE + e);
    int slot = atomicAdd(&g_cursor[c], 1);
    if (slot < CAP) g_src[(size_t)c * CAP + slot] = r;
}

// g_bufAh[n,:] = half( dinv[n] * (X[n,:K] @ W[K,64]) )
// 128 threads: 32 nodes x 64 cols per block; thread = 4 nodes (stride 8) x 4 cols
template<int K, bool FROM_EXT>
__global__ void __launch_bounds__(128) k_gemm(const float* __restrict__ Xext,
                                              const float* __restrict__ W) {
    constexpr int KC = 64;                    // k-chunk
    __shared__ float4 sW[KC * 16];            // [k][colquad]
    __shared__ float  sX[32 * KC];            // [node][k]
    const float* X = FROM_EXT ? Xext : (const float*)g_bufB;
    const int tid = threadIdx.x;
    const int node0 = blockIdx.x * 32;
    const int nn = min(32, NN - node0);
    const int tn = tid >> 4;                  // 0..7
    const int tc = tid & 15;                  // 0..15
    float4 acc[4];
    #pragma unroll
    for (int j = 0; j < 4; j++) acc[j] = make_float4(0.f, 0.f, 0.f, 0.f);

    for (int kc = 0; kc < K; kc += KC) {
        for (int i = tid; i < KC * 16; i += 128)
            sW[i] = ((const float4*)W)[(kc + (i >> 4)) * 16 + (i & 15)];
        for (int i = tid; i < 32 * (KC / 4); i += 128) {
            int nl = i / (KC / 4), kq = i % (KC / 4);
            float4 xv = (nl < nn)
                ? ((const float4*)X)[(size_t)(node0 + nl) * (K / 4) + (kc >> 2) + kq]
                : make_float4(0.f, 0.f, 0.f, 0.f);
            ((float4*)sX)[nl * (KC / 4) + kq] = xv;
        }
        __syncthreads();
        #pragma unroll 8
        for (int k = 0; k < KC; k++) {
            float4 w4 = sW[k * 16 + tc];
            #pragma unroll
            for (int j = 0; j < 4; j++) {
                float xv = sX[(tn + j * 8) * KC + k];
                acc[j].x = fmaf(xv, w4.x, acc[j].x);
                acc[j].y = fmaf(xv, w4.y, acc[j].y);
                acc[j].z = fmaf(xv, w4.z, acc[j].z);
                acc[j].w = fmaf(xv, w4.w, acc[j].w);
            }
        }
        __syncthreads();
    }
    #pragma unroll
    for (int j = 0; j < 4; j++) {
        int nl = tn + j * 8;
        if (nl < nn) {
            int node = node0 + nl;
            float s = rsqrtf((float)g_cursor[node] + 1.0f);
            float4 v = acc[j];
            __half2 lo = __floats2half2_rn(v.x * s, v.y * s);
            __half2 hi = __floats2half2_rn(v.z * s, v.w * s);
            uint2 pk = make_uint2(*(unsigned*)&lo, *(unsigned*)&hi);
            ((uint2*)g_bufAh)[node * 16 + tc] = pk;
        }
    }
}

// full warp per node: out = relu( dinv[c]*(h'[c] + sum h'[src]) + b )
// lane holds half2 (2 dims); edge ids broadcast-read by all lanes; x4 unroll
__global__ void k_aggr(const float* __restrict__ b, int fuse_pool,
                       const void* __restrict__ batch) {
    const int lane = threadIdx.x & 31;
    const int node = blockIdx.x * (blockDim.x >> 5) + (threadIdx.x >> 5);
    if (node >= NN) return;
    const __half2* __restrict__ h2 = (const __half2*)g_bufAh;  // row = 32 half2
    float2 acc = __half22float2(h2[node * 32 + lane]);          // self-loop h'
    const int cnt = g_cursor[node];
    const int deg = min(cnt, CAP);
    const int* __restrict__ bucket = &g_src[(size_t)node * CAP];
    int k = 0;
    for (; k + 4 <= deg; k += 4) {
        int r0 = __ldg(bucket + k);
        int r1 = __ldg(bucket + k + 1);
        int r2 = __ldg(bucket + k + 2);
        int r3 = __ldg(bucket + k + 3);
        __half2 v0 = h2[r0 * 32 + lane];
        __half2 v1 = h2[r1 * 32 + lane];
        __half2 v2 = h2[r2 * 32 + lane];
        __half2 v3 = h2[r3 * 32 + lane];
        float2 f0 = __half22float2(v0);
        float2 f1 = __half22float2(v1);
        float2 f2 = __half22float2(v2);
        float2 f3 = __half22float2(v3);
        acc.x += (f0.x + f1.x) + (f2.x + f3.x);
        acc.y += (f0.y + f1.y) + (f2.y + f3.y);
    }
    for (; k < deg; k++) {
        int r = __ldg(bucket + k);
        float2 f = __half22float2(h2[r * 32 + lane]);
        acc.x += f.x;
        acc.y += f.y;
    }
    const float d = rsqrtf((float)cnt + 1.0f);
    const float2 bb = ((const float2*)b)[lane];
    float2 v;
    v.x = fmaxf(fmaf(d, acc.x, bb.x), 0.f);
    v.y = fmaxf(fmaf(d, acc.y, bb.y), 0.f);
    if (!fuse_pool) {
        ((float2*)g_bufB)[node * 32 + lane] = v;
    } else {
        int g = g_b64 ? (int)((const long long*)batch)[node]
                      : ((const int*)batch)[node];
        float* ps = &g_psum[g * HID + lane * 2];
        atomicAdd(ps + 0, v.x);
        atomicAdd(ps + 1, v.y);
        if (lane == 0) atomicAdd(&g_pcnt[g], 1.0f);
    }
}

__global__ void k_mlp(const float* __restrict__ Wl1, const float* __restrict__ bl1,
                      const float* __restrict__ Wl2, const float* __restrict__ bl2,
                      float* __restrict__ out) {
    int g = threadIdx.x;
    if (g >= NG) return;
    float inv = 1.0f / fmaxf(g_pcnt[g], 1.0f);
    float mean[HID];
    #pragma unroll
    for (int k = 0; k < HID; k++) mean[k] = g_psum[g * HID + k] * inv;
    float o = bl2[0];
    #pragma unroll
    for (int j = 0; j < 16; j++) {
        float hj = bl1[j];
        #pragma unroll
        for (int k = 0; k < HID; k++) hj = fmaf(mean[k], Wl1[k * 16 + j], hj);
        o = fmaf(hj, Wl2[j], o);
    }
    out[g] = o;
}

// ---------------- launch ----------------
extern "C" void kernel_launch(void* const* d_in, const int* in_sizes, int n_in,
                              void* d_out, int out_size) {
    const float* x     = (const float*)d_in[0];
    const void*  ei    = d_in[1];
    const void*  batch = d_in[2];
    const float* W1 = (const float*)d_in[3];
    const float* b1 = (const float*)d_in[4];
    const float* W2 = (const float*)d_in[5];
    const float* b2 = (const float*)d_in[6];
    const float* W3 = (const float*)d_in[7];
    const float* b3 = (const float*)d_in[8];
    const float* Wl1 = (const float*)d_in[9];
    const float* bl1 = (const float*)d_in[10];
    const float* Wl2 = (const float*)d_in[11];
    const float* bl2 = (const float*)d_in[12];
    float* out = (float*)d_out;

    // zero the small scratch via memset (graph-capturable)
    void* curPtr;  cudaGetSymbolAddress(&curPtr,  g_cursor);
    void* psumPtr; cudaGetSymbolAddress(&psumPtr, g_psum);
    void* pcntPtr; cudaGetSymbolAddress(&pcntPtr, g_pcnt);
    cudaMemsetAsync(curPtr,  0, NN * sizeof(int));
    cudaMemsetAsync(psumPtr, 0, NG * HID * sizeof(float));
    cudaMemsetAsync(pcntPtr, 0, NG * sizeof(float));

    const int T = 512;
    k_detect<<<1, 32>>>(ei, batch);
    k_fill<<<(NE + T - 1) / T, T>>>(ei);

    const int gemmBlocks = (NN + 31) / 32;
    const int aggrBlocks = (NN + 7) / 8;    // 8 warps/block

    k_gemm<128, true ><<<gemmBlocks, 128>>>(x, W1);
    k_aggr<<<aggrBlocks, 256>>>(b1, 0, batch);
    k_gemm<64,  false><<<gemmBlocks, 128>>>(nullptr, W2);
    k_aggr<<<aggrBlocks, 256>>>(b2, 0, batch);
    k_gemm<64,  false><<<gemmBlocks, 128>>>(nullptr, W3);
    k_aggr<<<aggrBlocks, 256>>>(b3, 1, batch);   // fused mean-pool

    k_mlp<<<1, NG>>>(Wl1, bl1, Wl2, bl2, out);
}